// round 8
// baseline (speedup 1.0000x reference)
#include <cuda_runtime.h>

#define NTHREADS 256
#define SAMPLES  32
#define HDIM     50
#define G4       256           // 64 units * 4 gates, cols 4j+g
#define TSTEPS   256
#define HROW     68            // floats per h row: 32 dup pairs (64) + 4 pad
#define HBUF     (50*HROW)
#define XROW     68
#define XBUF     (32*XROW)

typedef unsigned long long ull;

__device__ __forceinline__ ull pack2(float lo, float hi) {
    ull r; asm("mov.b64 %0, {%1,%2};" : "=l"(r) : "f"(lo), "f"(hi)); return r;
}
__device__ __forceinline__ void unpack2(ull v, float& lo, float& hi) {
    asm("mov.b64 {%0,%1}, %2;" : "=f"(lo), "=f"(hi) : "l"(v));
}
__device__ __forceinline__ ull fma2(ull a, ull b, ull c) {
    ull d; asm("fma.rn.f32x2 %0, %1, %2, %3;" : "=l"(d) : "l"(a), "l"(b), "l"(c)); return d;
}
__device__ __forceinline__ float sigmoidf_(float x) {
    return __fdividef(1.f, 1.f + __expf(-x));
}
__device__ __forceinline__ float tanhf_(float x) {
    return fmaf(2.f, sigmoidf_(2.f * x), -1.f);
}

// Dynamic shared layout (floats):
//  Ws  [51*256] : rows 0..49 = W_hh (col 4j+g), row 50 = W_ih; zeros j>=50
//  bbv [256]    : b_ih + b_hh (col 4j+g)
//  hb  [2*50*68]: double-buffered h, rows [k][(s,s) dup pairs]
//  xs  [2*32*68]: double-buffered x tiles, rows [tt][(s,s) dup pairs]
#define OFF_WS  0
#define OFF_BB  (51*G4)
#define OFF_HB  (OFF_BB + G4)
#define OFF_XS  (OFF_HB + 2*HBUF)
#define SMEM_FLOATS (OFF_XS + 2*XBUF)

__global__ void __launch_bounds__(NTHREADS, 1) lstm_q_kernel(
    const float* __restrict__ x,    const float* __restrict__ W_ih,
    const float* __restrict__ W_hh, const float* __restrict__ b_ih,
    const float* __restrict__ b_hh, const float* __restrict__ Wp,
    const float* __restrict__ bp,   const float* __restrict__ qw,
    const float* __restrict__ Wo,   const float* __restrict__ bo,
    float* __restrict__ out)
{
    extern __shared__ float sm[];
    float* Ws  = sm + OFF_WS;
    float* bbv = sm + OFF_BB;
    float* hb  = sm + OFF_HB;
    float* xs  = sm + OFF_XS;

    const int tid   = threadIdx.x;
    const int lane  = tid & 31;
    const int warp  = tid >> 5;
    const int ug    = warp & 1;            // unit group
    const int sg    = warp >> 1;           // sample group (8 samples)
    const int j     = 32 * ug + lane;      // this thread's hidden unit
    const int sb    = 8 * sg;              // first sample
    const int bbase = blockIdx.x * SAMPLES;

    // ---- stage weights into shared ----
    for (int idx = tid; idx < 51 * G4; idx += NTHREADS) {
        int k = idx >> 8, c = idx & 255;
        int jj = c >> 2, g = c & 3;
        float v = 0.f;
        if (jj < HDIM) {
            if (k < HDIM)      v = W_hh[(g * HDIM + jj) * HDIM + k];
            else               v = W_ih[g * HDIM + jj];
        }
        Ws[idx] = v;
    }
    for (int idx = tid; idx < G4; idx += NTHREADS) {
        int jj = idx >> 2, g = idx & 3;
        bbv[idx] = (jj < HDIM) ? (b_ih[g * HDIM + jj] + b_hh[g * HDIM + jj]) : 0.f;
    }
    for (int idx = tid; idx < 2 * HBUF; idx += NTHREADS) hb[idx] = 0.f;
    // prefill x tile 0: coalesced read, transposed duplicated store
    for (int idx = tid; idx < 32 * 32; idx += NTHREADS) {
        int ss = idx >> 5, tt = idx & 31;
        float v = x[(bbase + ss) * TSTEPS + tt];
        *(ull*)(xs + tt * XROW + 2 * ss) = pack2(v, v);
    }
    __syncthreads();

    // persistent per-thread constants: bias and W_ih as (i,f),(g,o) packed pairs
    ulonglong2 bpair = *(const ulonglong2*)(bbv + 4 * j);          // (bi,bf),(bg,bo)
    ulonglong2 xwp   = *(const ulonglong2*)(Ws + 50 * G4 + 4 * j); // (wi,wf),(wg,wo)

    float c_st[8];
    #pragma unroll
    for (int i = 0; i < 8; i++) c_st[i] = 0.f;

    int buf = 0;

    for (int t = 0; t < TSTEPS; t++) {
        __syncthreads();               // prev-step h writes (+ prev refill) visible

        if ((t & 31) == 0 && t + 32 < TSTEPS) {
            float* xd = xs + (((t >> 5) & 1) ^ 1) * XBUF;
            for (int idx = tid; idx < 32 * 32; idx += NTHREADS) {
                int ss = idx >> 5, tt = idx & 31;
                float v = x[(bbase + ss) * TSTEPS + t + 32 + tt];
                *(ull*)(xd + tt * XROW + 2 * ss) = pack2(v, v);
            }
        }

        const float* hB   = hb + buf * HBUF;
        const float* xrow = xs + ((t >> 5) & 1) * XBUF + (t & 31) * XROW + 2 * sb;

        ull acc_if[8], acc_go[8];
        #pragma unroll
        for (int s2 = 0; s2 < 8; s2++) { acc_if[s2] = bpair.x; acc_go[s2] = bpair.y; }

        #pragma unroll 10
        for (int k = 0; k < 50; k++) {
            ulonglong2 wp = *(const ulonglong2*)(Ws + k * G4 + 4 * j); // dense, no movs
            const float* hr = hB + k * HROW + 2 * sb;
            ulonglong2 h01 = *(const ulonglong2*)(hr + 0);   // bcast: (h0,h0),(h1,h1)
            ulonglong2 h23 = *(const ulonglong2*)(hr + 4);
            ulonglong2 h45 = *(const ulonglong2*)(hr + 8);
            ulonglong2 h67 = *(const ulonglong2*)(hr + 12);
            ull hp[8] = { h01.x, h01.y, h23.x, h23.y, h45.x, h45.y, h67.x, h67.y };
            #pragma unroll
            for (int s2 = 0; s2 < 8; s2++) {
                acc_if[s2] = fma2(hp[s2], wp.x, acc_if[s2]);
                acc_go[s2] = fma2(hp[s2], wp.y, acc_go[s2]);
            }
        }
        // x contribution (row 50 weights persistent)
        {
            ulonglong2 x01 = *(const ulonglong2*)(xrow + 0);
            ulonglong2 x23 = *(const ulonglong2*)(xrow + 4);
            ulonglong2 x45 = *(const ulonglong2*)(xrow + 8);
            ulonglong2 x67 = *(const ulonglong2*)(xrow + 12);
            ull xp[8] = { x01.x, x01.y, x23.x, x23.y, x45.x, x45.y, x67.x, x67.y };
            #pragma unroll
            for (int s2 = 0; s2 < 8; s2++) {
                acc_if[s2] = fma2(xp[s2], xwp.x, acc_if[s2]);
                acc_go[s2] = fma2(xp[s2], xwp.y, acc_go[s2]);
            }
        }

        // ---- gates: unit j, samples sb..sb+7 ----
        float* hn = hb + (buf ^ 1) * HBUF + j * HROW + 2 * sb;
        float hv[8];
        #pragma unroll
        for (int s2 = 0; s2 < 8; s2++) {
            float zi, zf, zg, zo;
            unpack2(acc_if[s2], zi, zf);
            unpack2(acc_go[s2], zg, zo);
            float ig = sigmoidf_(zi);
            float fg = sigmoidf_(zf);
            float gg = tanhf_(zg);
            float og = sigmoidf_(zo);
            float c  = fmaf(fg, c_st[s2], ig * gg);
            c_st[s2] = c;
            hv[s2]   = og * tanhf_(c);
        }
        if (j < HDIM) {
            #pragma unroll
            for (int q = 0; q < 4; q++) {
                ulonglong2 w2;
                w2.x = pack2(hv[2*q],   hv[2*q]);
                w2.y = pack2(hv[2*q+1], hv[2*q+1]);
                *(ulonglong2*)(hn + 4 * q) = w2;    // STS.128, conflict-free
            }
        }
        buf ^= 1;
    }

    __syncthreads();   // all final-h writes visible

    // ---------------- quantum head: 1 thread per sample ----------------
    if (tid < SAMPLES) {
        const float* hfin = hb + buf * HBUF + 2 * tid;   // h[k][(tid,tid)] stride HROW

        float ang[4];
        #pragma unroll
        for (int w = 0; w < 4; w++) {
            float a = bp[w];
            for (int k = 0; k < HDIM; k++) a = fmaf(Wp[w * HDIM + k], hfin[k * HROW], a);
            ang[w] = tanhf_(a) * 1.5707963267948966f;
        }

        float re[16], im[16];
        #pragma unroll
        for (int i = 0; i < 16; i++) { re[i] = 0.f; im[i] = 0.f; }
        re[0] = 1.f;

        // RX embedding (wire w <-> bit 3-w)
        #pragma unroll
        for (int w = 0; w < 4; w++) {
            float sw, cw;
            sincosf(0.5f * ang[w], &sw, &cw);
            const int m = 8 >> w;
            #pragma unroll
            for (int i0 = 0; i0 < 16; i0++) {
                if (!(i0 & m)) {
                    int i1 = i0 | m;
                    float r0 = re[i0], q0 = im[i0], r1 = re[i1], q1 = im[i1];
                    re[i0] = cw * r0 + sw * q1;  im[i0] = cw * q0 - sw * r1;
                    re[i1] = cw * r1 + sw * q0;  im[i1] = cw * q1 - sw * r0;
                }
            }
        }

        // StronglyEntanglingLayers
        #pragma unroll
        for (int l = 0; l < 2; l++) {
            #pragma unroll
            for (int w = 0; w < 4; w++) {
                const float* q = qw + (l * 4 + w) * 3;
                float phi = q[0], th = q[1], om = q[2];
                float st_, ct_; sincosf(0.5f * th, &st_, &ct_);
                float sa, ca;   sincosf(0.5f * (phi + om), &sa, &ca);
                float sb2, cb2; sincosf(0.5f * (phi - om), &sb2, &cb2);
                float u00r =  ct_ * ca,  u00i = -ct_ * sa;
                float u01r = -st_ * cb2, u01i = -st_ * sb2;
                float u10r =  st_ * cb2, u10i = -st_ * sb2;
                float u11r =  ct_ * ca,  u11i =  ct_ * sa;
                const int m = 8 >> w;
                #pragma unroll
                for (int i0 = 0; i0 < 16; i0++) {
                    if (!(i0 & m)) {
                        int i1 = i0 | m;
                        float r0 = re[i0], q0 = im[i0], r1 = re[i1], q1 = im[i1];
                        re[i0] = u00r*r0 - u00i*q0 + u01r*r1 - u01i*q1;
                        im[i0] = u00r*q0 + u00i*r0 + u01r*q1 + u01i*r1;
                        re[i1] = u10r*r0 - u10i*q0 + u11r*r1 - u11i*q1;
                        im[i1] = u10r*q0 + u10i*r0 + u11r*q1 + u11i*r1;
                    }
                }
            }
            const int r = (l % 3) + 1;
            #pragma unroll
            for (int w = 0; w < 4; w++) {
                const int cm = 8 >> w;
                const int tm = 8 >> ((w + r) & 3);
                #pragma unroll
                for (int i0 = 0; i0 < 16; i0++) {
                    if ((i0 & cm) && !(i0 & tm)) {
                        int i1 = i0 | tm;
                        float tr = re[i0]; re[i0] = re[i1]; re[i1] = tr;
                        float ti = im[i0]; im[i0] = im[i1]; im[i1] = ti;
                    }
                }
            }
        }

        float o = bo[0];
        #pragma unroll
        for (int w = 0; w < 4; w++) {
            const int m = 8 >> w;
            float ev = 0.f;
            #pragma unroll
            for (int i = 0; i < 16; i++) {
                float p = re[i] * re[i] + im[i] * im[i];
                ev += (i & m) ? -p : p;
            }
            o = fmaf(Wo[w], ev, o);
        }
        out[bbase + tid] = o;
    }
}

extern "C" void kernel_launch(void* const* d_in, const int* in_sizes, int n_in,
                              void* d_out, int out_size) {
    const float* x    = (const float*)d_in[0];
    const float* W_ih = (const float*)d_in[1];
    const float* W_hh = (const float*)d_in[2];
    const float* b_ih = (const float*)d_in[3];
    const float* b_hh = (const float*)d_in[4];
    const float* Wp   = (const float*)d_in[5];
    const float* bp   = (const float*)d_in[6];
    const float* qw   = (const float*)d_in[7];
    const float* Wo   = (const float*)d_in[8];
    const float* bo   = (const float*)d_in[9];
    float* out = (float*)d_out;

    const size_t smem = SMEM_FLOATS * sizeof(float);
    cudaFuncSetAttribute(lstm_q_kernel, cudaFuncAttributeMaxDynamicSharedMemorySize, (int)smem);

    lstm_q_kernel<<<4096 / SAMPLES, NTHREADS, smem>>>(
        x, W_ih, W_hh, b_ih, b_hh, Wp, bp, qw, Wo, bo, out);
}